// round 13
// baseline (speedup 1.0000x reference)
#include <cuda_runtime.h>
#include <cstdint>

#define Bk   64
#define Sk   4096
#define EMBk 20
#define HIDk 20
#define VOC  256

// Scratch (static device allocations are allowed; runtime allocs are not)
__device__ float g_xproj[Bk * Sk * 80];   // x@W_ih.T + b (sigmoid rows pre-halved)
__device__ float g_dist[Bk * 40];         // sum over S of emb (for dist_vector)
__device__ float g_h[Bk * 20];            // final LSTM hidden state
__device__ int   g_flag[Bk * 16];         // producer->consumer chunk flags

typedef unsigned long long u64;

__device__ __forceinline__ float fsig(float x) {
    return __fdividef(1.f, 1.f + __expf(-x));
}

// HW tanh (MUFU.TANH): lat ~16 vs ~44 for exp/div chain
__device__ __forceinline__ float ftanh_hw(float x) {
    float y; asm("tanh.approx.f32 %0, %1;" : "=f"(y) : "f"(x)); return y;
}

// packed f32x2 helpers (Blackwell packed fp32 pipe — PTX-only encodings)
__device__ __forceinline__ u64 pk2(float lo, float hi) {
    u64 r; asm("mov.b64 %0, {%1, %2};" : "=l"(r) : "f"(lo), "f"(hi)); return r;
}
__device__ __forceinline__ u64 ffma2(u64 a, u64 b, u64 c) {
    u64 d; asm("fma.rn.f32x2 %0, %1, %2, %3;" : "=l"(d) : "l"(a), "l"(b), "l"(c));
    return d;
}
__device__ __forceinline__ u64 fadd2(u64 a, u64 b) {
    u64 d; asm("add.rn.f32x2 %0, %1, %2;" : "=l"(d) : "l"(a), "l"(b));
    return d;
}
__device__ __forceinline__ float hadd2(u64 v) {
    float lo, hi; asm("mov.b64 {%0, %1}, %2;" : "=f"(lo), "=f"(hi) : "l"(v));
    return lo + hi;
}

// ---------------------------------------------------------------------------
// init: zero dist accumulator + producer flags (deterministic per launch)
// ---------------------------------------------------------------------------
__global__ void initk() {
    int i = blockIdx.x * blockDim.x + threadIdx.x;
    if (i < Bk * 40) g_dist[i] = 0.f;
    if (i < Bk * 16) g_flag[i] = 0;
}

// ---------------------------------------------------------------------------
// FUSED kernel: blocks 0..63 = phase2 LSTM consumers (one warp per batch),
// blocks 64..1087 = phase1 producers (sx-major: chunk-0 data produced first).
// Producer publishes each (b, 256-step region) with release-flag; consumer
// acquire-spins at 8-chunk boundaries before cp.async.
// ---------------------------------------------------------------------------
__global__ void __launch_bounds__(256) fused12(
    const int* __restrict__ inp,
    const float* __restrict__ pc_emb, const float* __restrict__ addr_emb,
    const float* __restrict__ enc_W, const float* __restrict__ enc_b,
    const float* __restrict__ W_ih, const float* __restrict__ b_ih,
    const float* __restrict__ b_hh,
    const float* __restrict__ h0, const float* __restrict__ c0,
    const float* __restrict__ W_hh)
{
    // -------------------- phase2 consumer path (blocks 0..63) ---------------
    if (blockIdx.x < 64) {
        __shared__ __align__(16) float xs[2][32 * 80];
        if (threadIdx.x >= 32) return;
        const int lane = threadIdx.x;
        const int b = blockIdx.x;

        const int r0 = (lane < 20) ? lane      : 40 + lane;           // 60..71
        const int r1 = (lane < 20) ? 20 + lane : (lane < 28 ? 52 + lane : 79);
        const int r2 = (lane < 20) ? 40 + lane : 79;

        u64 w0[10], w1[10], w2s[10];
        #pragma unroll
        for (int k = 0; k < 10; k++) {
            float2 a;
            a = ((const float2*)(W_hh + r0 * 20))[k]; w0[k]  = pk2(0.5f * a.x, 0.5f * a.y);
            a = ((const float2*)(W_hh + r1 * 20))[k]; w1[k]  = pk2(0.5f * a.x, 0.5f * a.y);
            a = ((const float2*)(W_hh + r2 * 20))[k]; w2s[k] = pk2(a.x, a.y);
        }
        float hn = (lane < 20) ? h0[b * 20 + lane] : 0.f;
        float c  = (lane < 20) ? c0[b * 20 + lane] : 0.f;

        const float4* src = (const float4*)g_xproj + (size_t)b * (Sk * 20);
        unsigned sm0 = (unsigned)__cvta_generic_to_shared(&xs[0][0]);

        auto refill = [&](int chunk, int buf) {
            if ((chunk & 7) == 0) {           // new producer region: acquire
                if (lane == 0) {
                    const int* fp = &g_flag[b * 16 + (chunk >> 3)];
                    int v;
                    do {
                        asm volatile("ld.acquire.gpu.global.s32 %0, [%1];"
                                     : "=r"(v) : "l"(fp) : "memory");
                    } while (v == 0);
                }
                __syncwarp();
            }
            unsigned d = sm0 + (unsigned)buf * (2560u * 4u);
            const float4* s = src + chunk * 640;
            #pragma unroll
            for (int q = 0; q < 20; q++) {
                unsigned da = d + (unsigned)(lane + 32 * q) * 16u;
                const float4* sa = s + lane + 32 * q;
                asm volatile("cp.async.cg.shared.global [%0], [%1], 16;"
                             :: "r"(da), "l"(sa));
            }
            asm volatile("cp.async.commit_group;");
        };

        refill(0, 0);
        refill(1, 1);
        asm volatile("cp.async.wait_group 1;");
        __syncwarp();

        const u64 Z2 = pk2(0.f, 0.f);
        const int NC = Sk / 32;
        for (int ci = 0; ci < NC; ci++) {
            const float* xb = &xs[ci & 1][0];
            #pragma unroll 2
            for (int t = 0; t < 32; t++) {
                const float* xt = xb + t * 80;
                float x0 = xt[r0], x1 = xt[r1], x2 = xt[r2];
                u64 aA = pk2(x0, 0.f), aB = Z2;
                u64 bA = pk2(x1, 0.f), bB = Z2;
                u64 cA = pk2(x2, 0.f), cB = Z2;
                #pragma unroll
                for (int k = 0; k < 5; k++) {
                    float lo0 = __shfl_sync(0xffffffffu, hn, 2 * k);
                    float hi0 = __shfl_sync(0xffffffffu, hn, 2 * k + 1);
                    u64 hh0 = pk2(lo0, hi0);
                    float lo1 = __shfl_sync(0xffffffffu, hn, 2 * k + 10);
                    float hi1 = __shfl_sync(0xffffffffu, hn, 2 * k + 11);
                    u64 hh1 = pk2(lo1, hi1);
                    aA = ffma2(w0[k],      hh0, aA);
                    bA = ffma2(w1[k],      hh0, bA);
                    cA = ffma2(w2s[k],     hh0, cA);
                    aB = ffma2(w0[k + 5],  hh1, aB);
                    bB = ffma2(w1[k + 5],  hh1, bB);
                    cB = ffma2(w2s[k + 5], hh1, cB);
                }
                float s0 = __fmaf_rn(0.5f, ftanh_hw(hadd2(fadd2(aA, aB))), 0.5f);
                float s1 = __fmaf_rn(0.5f, ftanh_hw(hadd2(fadd2(bA, bB))), 0.5f);
                float tg = ftanh_hw(hadd2(fadd2(cA, cB)));

                float oA = __shfl_sync(0xffffffffu, s0, lane + 20);
                float oB = __shfl_sync(0xffffffffu, s1, lane + 8);
                float o  = (lane < 12) ? oA : oB;

                c  = __fmaf_rn(s1, c, s0 * tg);      // f*c + i*g
                hn = o * ftanh_hw(c);                // o * tanh(c)
            }
            if (ci + 1 < NC) {
                asm volatile("cp.async.wait_group 0;");
                __syncwarp();
                if (ci + 2 < NC) refill(ci + 2, ci & 1);
            }
        }
        if (lane < 20) g_h[b * 20 + lane] = hn;
        return;
    }

    // -------------------- phase1 producer path (blocks 64..1087) ------------
    {
        __shared__ __align__(16) float sWe[20 * 80];
        __shared__ __align__(16) float sWih[80 * 40];
        __shared__ float sbe[20];
        __shared__ float sbs[80];
        __shared__ float ssum[40];

        int idx = blockIdx.x - 64;
        int sx = idx >> 6;          // 0..15 (sx-major: region 0 first)
        int b  = idx & 63;

        int tid = threadIdx.x;
        for (int i = tid; i < 1600; i += 256) sWe[i] = enc_W[i];
        for (int i = tid; i < 3200; i += 256) {
            int row = i / 40;
            float sc = (row >= 40 && row < 60) ? 1.f : 0.5f;
            sWih[i] = W_ih[i] * sc;
        }
        if (tid < 20) sbe[tid] = enc_b[tid];
        if (tid < 80) {
            float sc = (tid >= 40 && tid < 60) ? 1.f : 0.5f;
            sbs[tid] = (b_ih[tid] + b_hh[tid]) * sc;
        }
        if (tid < 40) ssum[tid] = 0.f;
        __syncthreads();

        int s = sx * 256 + tid;
        int2 pv = ((const int2*)inp)[b * Sk + s];

        float emb[40];

        #pragma unroll
        for (int p = 0; p < 2; p++) {
            unsigned val = (unsigned)(p ? pv.y : pv.x);
            const float* tab = p ? addr_emb : pc_emb;
            u64 acc2[20];
            #pragma unroll
            for (int o = 0; o < 20; o++) acc2[o] = pk2(sbe[o], 0.f);

            #pragma unroll 1
            for (int i = 0; i < 4; i++) {
                unsigned byt = (val >> (24 - 8 * i)) & 0xFFu;
                const ulonglong2* row =
                    (const ulonglong2*)(tab + (i * 256 + (int)byt) * 20);
                ulonglong2 G0 = __ldg(row),     G1 = __ldg(row + 1),
                           G2 = __ldg(row + 2), G3 = __ldg(row + 3),
                           G4 = __ldg(row + 4);
                #pragma unroll
                for (int o = 0; o < 20; o++) {
                    const ulonglong2* wo =
                        (const ulonglong2*)(sWe + o * 80 + i * 20);
                    ulonglong2 w0 = wo[0], w1 = wo[1], w2 = wo[2], w3 = wo[3],
                               w4 = wo[4];
                    u64 a = acc2[o];
                    a = ffma2(w0.x, G0.x, a); a = ffma2(w0.y, G0.y, a);
                    a = ffma2(w1.x, G1.x, a); a = ffma2(w1.y, G1.y, a);
                    a = ffma2(w2.x, G2.x, a); a = ffma2(w2.y, G2.y, a);
                    a = ffma2(w3.x, G3.x, a); a = ffma2(w3.y, G3.y, a);
                    a = ffma2(w4.x, G4.x, a); a = ffma2(w4.y, G4.y, a);
                    acc2[o] = a;
                }
            }
            #pragma unroll
            for (int o = 0; o < 20; o++) emb[p * 20 + o] = fsig(hadd2(acc2[o]));
        }

        // x-projection: 80 outputs, K = 40 packed as 20 f32x2 pairs.
        {
            u64 x2[20];
            #pragma unroll
            for (int m = 0; m < 20; m++) x2[m] = pk2(emb[2 * m], emb[2 * m + 1]);

            float4* outp = (float4*)g_xproj + (b * Sk + s) * 20;
            #pragma unroll 1
            for (int jq = 0; jq < 20; jq++) {
                u64 A0 = pk2(sbs[jq * 4 + 0], 0.f);
                u64 A1 = pk2(sbs[jq * 4 + 1], 0.f);
                u64 A2 = pk2(sbs[jq * 4 + 2], 0.f);
                u64 A3 = pk2(sbs[jq * 4 + 3], 0.f);
                const u64* w0 = (const u64*)(sWih + (jq * 4 + 0) * 40);
                const u64* w1 = (const u64*)(sWih + (jq * 4 + 1) * 40);
                const u64* w2 = (const u64*)(sWih + (jq * 4 + 2) * 40);
                const u64* w3 = (const u64*)(sWih + (jq * 4 + 3) * 40);
                #pragma unroll
                for (int m = 0; m < 20; m++) {
                    u64 xm = x2[m];
                    A0 = ffma2(w0[m], xm, A0);
                    A1 = ffma2(w1[m], xm, A1);
                    A2 = ffma2(w2[m], xm, A2);
                    A3 = ffma2(w3[m], xm, A3);
                }
                outp[jq] = make_float4(hadd2(A0), hadd2(A1), hadd2(A2),
                                       hadd2(A3));
            }
        }

        // dist_vector accumulation
        #pragma unroll
        for (int e = 0; e < 40; e++) {
            float v2 = emb[e];
            v2 += __shfl_xor_sync(0xffffffffu, v2, 16);
            v2 += __shfl_xor_sync(0xffffffffu, v2, 8);
            v2 += __shfl_xor_sync(0xffffffffu, v2, 4);
            v2 += __shfl_xor_sync(0xffffffffu, v2, 2);
            v2 += __shfl_xor_sync(0xffffffffu, v2, 1);
            if ((tid & 31) == 0) atomicAdd(&ssum[e], v2);
        }
        __syncthreads();
        if (tid < 40) atomicAdd(&g_dist[b * 40 + tid], ssum[tid]);

        // publish this (b, sx) region: all 256 positions written
        __syncthreads();
        __threadfence();
        if (tid == 0) {
            asm volatile("st.release.gpu.global.s32 [%0], %1;"
                         :: "l"(&g_flag[b * 16 + sx]), "r"(1) : "memory");
        }
    }
}

// ---------------------------------------------------------------------------
// Phase 3a: logits + batch-axis softmax. One warp per (k, v); lane handles
// batches (lane, lane+32). Writes probs at out[0..], logits at out[65536..].
// ---------------------------------------------------------------------------
__global__ void __launch_bounds__(256) phase3a(
    const float* __restrict__ dec_W, const float* __restrict__ dec_b,
    float* __restrict__ out)
{
    __shared__ float hs[64 * 20];
    for (int i = threadIdx.x; i < 1280; i += 256) hs[i] = g_h[i];
    __syncthreads();

    int warp = blockIdx.x * 8 + (threadIdx.x >> 5);
    int lane = threadIdx.x & 31;
    int k = warp >> 8, v = warp & 255;

    const float* wrow = dec_W + (k * 256 + v) * 20;
    float w[20];
    #pragma unroll
    for (int e = 0; e < 20; e++) w[e] = __ldg(wrow + e);
    float bb = __ldg(dec_b + k * 256 + v);

    int b0 = lane, b1 = lane + 32;
    float l0 = bb, l1 = bb;
    #pragma unroll
    for (int e = 0; e < 20; e++) {
        l0 += hs[b0 * 20 + e] * w[e];
        l1 += hs[b1 * 20 + e] * w[e];
    }
    out[65536 + (k * 64 + b0) * 256 + v] = l0;
    out[65536 + (k * 64 + b1) * 256 + v] = l1;

    float s0 = l0 / 0.001f, s1 = l1 / 0.001f;   // exact div, mirrors reference
    float m = fmaxf(s0, s1);
    #pragma unroll
    for (int o = 16; o > 0; o >>= 1) m = fmaxf(m, __shfl_xor_sync(0xffffffffu, m, o));
    float p0 = __expf(s0 - m), p1 = __expf(s1 - m);
    float sum = p0 + p1;
    #pragma unroll
    for (int o = 16; o > 0; o >>= 1) sum += __shfl_xor_sync(0xffffffffu, sum, o);
    float inv = __fdividef(1.f, sum);
    out[(k * 64 + b0) * 256 + v] = p0 * inv;
    out[(k * 64 + b1) * 256 + v] = p1 * inv;
}

// ---------------------------------------------------------------------------
// Phase 3b: byte_e = probs @ addr_emb, fe = encoder(byte_e), freq_rec head.
// One CTA per batch element.
// ---------------------------------------------------------------------------
__global__ void __launch_bounds__(128) phase3b(
    const float* __restrict__ addr_emb,
    const float* __restrict__ enc_W, const float* __restrict__ enc_b,
    const float* __restrict__ d1_W, const float* __restrict__ d1_b,
    const float* __restrict__ d2_W, const float* __restrict__ d2_b,
    float* __restrict__ out)
{
    __shared__ float ps[4 * 256];
    __shared__ float xv[80];
    __shared__ float fr_in[60];
    __shared__ float r1[10];

    int b = blockIdx.x, tid = threadIdx.x;
    for (int i = tid; i < 1024; i += 128) {
        int k = i >> 8, v = i & 255;
        ps[i] = out[(k * 64 + b) * 256 + v];
    }
    __syncthreads();

    if (tid < 80) {
        int k = tid / 20, e = tid % 20;
        float acc = 0.f;
        const float* ae = addr_emb + k * 256 * 20 + e;
        const float* pk = ps + k * 256;
        #pragma unroll 8
        for (int v = 0; v < 256; v++) acc += pk[v] * __ldg(ae + v * 20);
        xv[tid] = acc;
    }
    __syncthreads();

    if (tid < 20) {
        float a = enc_b[tid];
        #pragma unroll 8
        for (int e = 0; e < 80; e++) a += xv[e] * enc_W[tid * 80 + e];
        fr_in[tid] = fsig(a);
    }
    if (tid >= 64 && tid < 104) {
        int e = tid - 64;
        fr_in[20 + e] = g_dist[b * 40 + e] * (1.0f / 4096.0f);
    }
    __syncthreads();

    if (tid < 10) {
        float a = d1_b[tid];
        #pragma unroll
        for (int e = 0; e < 60; e++) a += fr_in[e] * d1_W[tid * 60 + e];
        r1[tid] = fmaxf(a, 0.f);
    }
    __syncthreads();

    if (tid < 2) {
        float a = d2_b[tid];
        #pragma unroll
        for (int e = 0; e < 10; e++) a += r1[e] * d2_W[tid * 10 + e];
        out[131072 + tid * 64 + b] = a;
    }
}

// ---------------------------------------------------------------------------
extern "C" void kernel_launch(void* const* d_in, const int* in_sizes, int n_in,
                              void* d_out, int out_size)
{
    const int*   inp      = (const int*)d_in[0];
    const float* h0       = (const float*)d_in[1];
    const float* c0       = (const float*)d_in[2];
    const float* pc_emb   = (const float*)d_in[3];
    const float* addr_emb = (const float*)d_in[4];
    const float* enc_W    = (const float*)d_in[5];
    const float* enc_b    = (const float*)d_in[6];
    const float* W_ih     = (const float*)d_in[7];
    const float* W_hh     = (const float*)d_in[8];
    const float* b_ih     = (const float*)d_in[9];
    const float* b_hh     = (const float*)d_in[10];
    const float* dec_W    = (const float*)d_in[11];
    const float* dec_b    = (const float*)d_in[12];
    const float* d1_W     = (const float*)d_in[13];
    const float* d1_b     = (const float*)d_in[14];
    const float* d2_W     = (const float*)d_in[15];
    const float* d2_b     = (const float*)d_in[16];
    float* out = (float*)d_out;

    initk<<<10, 256>>>();
    fused12<<<1088, 256>>>(inp, pc_emb, addr_emb, enc_W, enc_b,
                           W_ih, b_ih, b_hh, h0, c0, W_hh);
    phase3a<<<128, 256>>>(dec_W, dec_b, out);
    phase3b<<<64, 128>>>(addr_emb, enc_W, enc_b, d1_W, d1_b, d2_W, d2_b, out);
}

// round 14
// speedup vs baseline: 16.8500x; 16.8500x over previous
#include <cuda_runtime.h>
#include <cstdint>

#define Bk   64
#define Sk   4096
#define EMBk 20
#define HIDk 20
#define VOC  256

// Scratch (static device allocations are allowed; runtime allocs are not)
__device__ float g_xproj[Bk * Sk * 80];   // x@W_ih.T + b (sigmoid rows pre-halved)
__device__ float g_dist[Bk * 40];         // sum over S of emb (for dist_vector)
__device__ float g_h[Bk * 20];            // final LSTM hidden state
__device__ float g_ptab[2 * 4 * 256 * 20];// [tab][bytepos][byteval][o]: emb@W_i^T

typedef unsigned long long u64;

__device__ __forceinline__ float fsig(float x) {
    return __fdividef(1.f, 1.f + __expf(-x));
}

// HW tanh (MUFU.TANH): lat ~16 vs ~44 for exp/div chain
__device__ __forceinline__ float ftanh_hw(float x) {
    float y; asm("tanh.approx.f32 %0, %1;" : "=f"(y) : "f"(x)); return y;
}

// packed f32x2 helpers (Blackwell packed fp32 pipe — PTX-only encodings)
__device__ __forceinline__ u64 pk2(float lo, float hi) {
    u64 r; asm("mov.b64 %0, {%1, %2};" : "=l"(r) : "f"(lo), "f"(hi)); return r;
}
__device__ __forceinline__ u64 ffma2(u64 a, u64 b, u64 c) {
    u64 d; asm("fma.rn.f32x2 %0, %1, %2, %3;" : "=l"(d) : "l"(a), "l"(b), "l"(c));
    return d;
}
__device__ __forceinline__ u64 fadd2(u64 a, u64 b) {
    u64 d; asm("add.rn.f32x2 %0, %1, %2;" : "=l"(d) : "l"(a), "l"(b));
    return d;
}
__device__ __forceinline__ float hadd2(u64 v) {
    float lo, hi; asm("mov.b64 {%0, %1}, %2;" : "=f"(lo), "=f"(hi) : "l"(v));
    return lo + hi;
}

// ---------------------------------------------------------------------------
// init: zero the dist accumulator (must be deterministic per launch)
// ---------------------------------------------------------------------------
__global__ void initk() {
    int i = blockIdx.x * blockDim.x + threadIdx.x;
    if (i < Bk * 40) g_dist[i] = 0.f;
}

// ---------------------------------------------------------------------------
// prep: fold the encoder weight into the byte-embedding tables.
// g_ptab[t][i][v][o] = sum_k emb_t[i*256+v][k] * enc_W[o][i*20+k]
// 2048 rows x 20 outputs x 20-FMA dot: ~3 us. grid 8 x 256, 1 row/thread.
// ---------------------------------------------------------------------------
__global__ void __launch_bounds__(256) prep(
    const float* __restrict__ pc_emb, const float* __restrict__ addr_emb,
    const float* __restrict__ enc_W)
{
    int r = blockIdx.x * 256 + threadIdx.x;      // 0..2047
    int tab = r >> 10;
    int rem = r & 1023;
    int i = rem >> 8;                            // byte position 0..3
    const float* emb = (tab ? addr_emb : pc_emb) + rem * 20;
    float e[20];
    #pragma unroll
    for (int k = 0; k < 20; k++) e[k] = __ldg(emb + k);
    float* outp = g_ptab + r * 20;
    #pragma unroll 4
    for (int o = 0; o < 20; o++) {
        const float* w = enc_W + o * 80 + i * 20;
        float a = 0.f;
        #pragma unroll
        for (int k = 0; k < 20; k++) a += e[k] * __ldg(w + k);
        outp[o] = a;
    }
}

// ---------------------------------------------------------------------------
// Phase 1: byte-embedding via PRE-PROJECTED tables (encoder dot folded into
// g_ptab by prep — 4 gathered 20-float vector adds replace the 1600-FMA dot)
// + x-projection in packed fma.f32x2. Sigmoid-gate rows (j<40 or j>=60) of
// the projection PRE-SCALED by 0.5. grid (16,64).
// ---------------------------------------------------------------------------
__global__ void __launch_bounds__(256) phase1(
    const int* __restrict__ inp,
    const float* __restrict__ enc_b,
    const float* __restrict__ W_ih, const float* __restrict__ b_ih,
    const float* __restrict__ b_hh)
{
    __shared__ __align__(16) float sWih[80 * 40];
    __shared__ float sbe[20];
    __shared__ float sbs[80];
    __shared__ float ssum[40];

    int tid = threadIdx.x;
    for (int i = tid; i < 3200; i += 256) {
        int row = i / 40;
        float sc = (row >= 40 && row < 60) ? 1.f : 0.5f;
        sWih[i] = W_ih[i] * sc;
    }
    if (tid < 20) sbe[tid] = enc_b[tid];
    if (tid < 80) {
        float sc = (tid >= 40 && tid < 60) ? 1.f : 0.5f;
        sbs[tid] = (b_ih[tid] + b_hh[tid]) * sc;
    }
    if (tid < 40) ssum[tid] = 0.f;
    __syncthreads();

    int b = blockIdx.y;
    int s = blockIdx.x * 256 + tid;
    int2 pv = ((const int2*)inp)[b * Sk + s];

    float emb[40];

    #pragma unroll
    for (int p = 0; p < 2; p++) {
        unsigned val = (unsigned)(p ? pv.y : pv.x);
        const float* ptab = g_ptab + p * (4 * 256 * 20);
        float4 a0, a1, a2, a3, a4;
        {   // i = 0
            unsigned byt = (val >> 24) & 0xFFu;
            const float4* row = (const float4*)(ptab + (int)byt * 20);
            a0 = __ldg(row);     a1 = __ldg(row + 1); a2 = __ldg(row + 2);
            a3 = __ldg(row + 3); a4 = __ldg(row + 4);
        }
        #pragma unroll
        for (int i = 1; i < 4; i++) {
            unsigned byt = (val >> (24 - 8 * i)) & 0xFFu;
            const float4* row =
                (const float4*)(ptab + (i * 256 + (int)byt) * 20);
            float4 g0 = __ldg(row),     g1 = __ldg(row + 1),
                   g2 = __ldg(row + 2), g3 = __ldg(row + 3),
                   g4 = __ldg(row + 4);
            a0.x += g0.x; a0.y += g0.y; a0.z += g0.z; a0.w += g0.w;
            a1.x += g1.x; a1.y += g1.y; a1.z += g1.z; a1.w += g1.w;
            a2.x += g2.x; a2.y += g2.y; a2.z += g2.z; a2.w += g2.w;
            a3.x += g3.x; a3.y += g3.y; a3.z += g3.z; a3.w += g3.w;
            a4.x += g4.x; a4.y += g4.y; a4.z += g4.z; a4.w += g4.w;
        }
        float acc[20];
        acc[0]  = a0.x; acc[1]  = a0.y; acc[2]  = a0.z; acc[3]  = a0.w;
        acc[4]  = a1.x; acc[5]  = a1.y; acc[6]  = a1.z; acc[7]  = a1.w;
        acc[8]  = a2.x; acc[9]  = a2.y; acc[10] = a2.z; acc[11] = a2.w;
        acc[12] = a3.x; acc[13] = a3.y; acc[14] = a3.z; acc[15] = a3.w;
        acc[16] = a4.x; acc[17] = a4.y; acc[18] = a4.z; acc[19] = a4.w;
        #pragma unroll
        for (int o = 0; o < 20; o++)
            emb[p * 20 + o] = fsig(acc[o] + sbe[o]);
    }

    // x-projection: 80 outputs, K = 40 packed as 20 f32x2 pairs.
    {
        u64 x2[20];
        #pragma unroll
        for (int m = 0; m < 20; m++) x2[m] = pk2(emb[2 * m], emb[2 * m + 1]);

        float4* outp = (float4*)g_xproj + (b * Sk + s) * 20;
        #pragma unroll 1
        for (int jq = 0; jq < 20; jq++) {
            u64 A0 = pk2(sbs[jq * 4 + 0], 0.f);
            u64 A1 = pk2(sbs[jq * 4 + 1], 0.f);
            u64 A2 = pk2(sbs[jq * 4 + 2], 0.f);
            u64 A3 = pk2(sbs[jq * 4 + 3], 0.f);
            const u64* w0 = (const u64*)(sWih + (jq * 4 + 0) * 40);
            const u64* w1 = (const u64*)(sWih + (jq * 4 + 1) * 40);
            const u64* w2 = (const u64*)(sWih + (jq * 4 + 2) * 40);
            const u64* w3 = (const u64*)(sWih + (jq * 4 + 3) * 40);
            #pragma unroll
            for (int m = 0; m < 20; m++) {
                u64 xm = x2[m];
                A0 = ffma2(w0[m], xm, A0);
                A1 = ffma2(w1[m], xm, A1);
                A2 = ffma2(w2[m], xm, A2);
                A3 = ffma2(w3[m], xm, A3);
            }
            outp[jq] = make_float4(hadd2(A0), hadd2(A1), hadd2(A2), hadd2(A3));
        }
    }

    // dist_vector accumulation
    #pragma unroll
    for (int e = 0; e < 40; e++) {
        float v2 = emb[e];
        v2 += __shfl_xor_sync(0xffffffffu, v2, 16);
        v2 += __shfl_xor_sync(0xffffffffu, v2, 8);
        v2 += __shfl_xor_sync(0xffffffffu, v2, 4);
        v2 += __shfl_xor_sync(0xffffffffu, v2, 2);
        v2 += __shfl_xor_sync(0xffffffffu, v2, 1);
        if ((tid & 31) == 0) atomicAdd(&ssum[e], v2);
    }
    __syncthreads();
    if (tid < 40) atomicAdd(&g_dist[b * 40 + tid], ssum[tid]);
}

// ---------------------------------------------------------------------------
// Phase 2: sequential LSTM, ONE WARP per batch element — EXACT round-7 body
// (the measured optimum; all pairing/exchange restructurings lost).
// Slot mapping (3 dot slots cover all 80 gates):
//   slot0: lanes 0-19 -> i_l      lanes 20-31 -> o_{l-20} (rows 60-71)
//   slot1: lanes 0-19 -> f_l      lanes 20-27 -> o_{l-8}  (rows 72-79)
//   slot2: lanes 0-19 -> g_l      lanes 20-31 -> dummy (row 79)
// Inline SHFL h-broadcast overlapping the 2-way-tree fma.f32x2 chains;
// MUFU.TANH activations; sigmoid 0.5 pre-folded into W_hh rows and g_xproj.
// ---------------------------------------------------------------------------
__global__ void __launch_bounds__(32) phase2(
    const float* __restrict__ h0, const float* __restrict__ c0,
    const float* __restrict__ W_hh)
{
    __shared__ __align__(16) float xs[2][32 * 80];
    const int lane = threadIdx.x;
    const int b = blockIdx.x;

    const int r0 = (lane < 20) ? lane      : 40 + lane;               // 60..71
    const int r1 = (lane < 20) ? 20 + lane : (lane < 28 ? 52 + lane : 79);
    const int r2 = (lane < 20) ? 40 + lane : 79;

    // slot0/slot1 rows are ALL sigmoid rows -> pre-scale by 0.5 (tanh identity)
    u64 w0[10], w1[10], w2s[10];
    #pragma unroll
    for (int k = 0; k < 10; k++) {
        float2 a;
        a = ((const float2*)(W_hh + r0 * 20))[k]; w0[k]  = pk2(0.5f * a.x, 0.5f * a.y);
        a = ((const float2*)(W_hh + r1 * 20))[k]; w1[k]  = pk2(0.5f * a.x, 0.5f * a.y);
        a = ((const float2*)(W_hh + r2 * 20))[k]; w2s[k] = pk2(a.x, a.y);
    }
    float hn = (lane < 20) ? h0[b * 20 + lane] : 0.f;
    float c  = (lane < 20) ? c0[b * 20 + lane] : 0.f;

    const float4* src = (const float4*)g_xproj + (size_t)b * (Sk * 20);
    unsigned sm0 = (unsigned)__cvta_generic_to_shared(&xs[0][0]);

    auto refill = [&](int chunk, int buf) {
        unsigned d = sm0 + (unsigned)buf * (2560u * 4u);
        const float4* s = src + chunk * 640;
        #pragma unroll
        for (int q = 0; q < 20; q++) {
            unsigned da = d + (unsigned)(lane + 32 * q) * 16u;
            const float4* sa = s + lane + 32 * q;
            asm volatile("cp.async.cg.shared.global [%0], [%1], 16;"
                         :: "r"(da), "l"(sa));
        }
        asm volatile("cp.async.commit_group;");
    };

    refill(0, 0);
    refill(1, 1);
    asm volatile("cp.async.wait_group 1;");
    __syncwarp();

    const u64 Z2 = pk2(0.f, 0.f);
    const int NC = Sk / 32;
    for (int ci = 0; ci < NC; ci++) {
        const float* xb = &xs[ci & 1][0];
        #pragma unroll 2
        for (int t = 0; t < 32; t++) {
            const float* xt = xb + t * 80;
            // hoist x loads: LDS latency hides under the shfl stream
            float x0 = xt[r0], x1 = xt[r1], x2 = xt[r2];
            u64 aA = pk2(x0, 0.f), aB = Z2;
            u64 bA = pk2(x1, 0.f), bB = Z2;
            u64 cA = pk2(x2, 0.f), cB = Z2;
            // inline h-broadcast: shfl latency overlaps the fma.f32x2 chains.
            // 2-way tree per slot: k=0..4 -> *A, k=5..9 -> *B (independent).
            #pragma unroll
            for (int k = 0; k < 5; k++) {
                float lo0 = __shfl_sync(0xffffffffu, hn, 2 * k);
                float hi0 = __shfl_sync(0xffffffffu, hn, 2 * k + 1);
                u64 hh0 = pk2(lo0, hi0);
                float lo1 = __shfl_sync(0xffffffffu, hn, 2 * k + 10);
                float hi1 = __shfl_sync(0xffffffffu, hn, 2 * k + 11);
                u64 hh1 = pk2(lo1, hi1);
                aA = ffma2(w0[k],      hh0, aA);
                bA = ffma2(w1[k],      hh0, bA);
                cA = ffma2(w2s[k],     hh0, cA);
                aB = ffma2(w0[k + 5],  hh1, aB);
                bB = ffma2(w1[k + 5],  hh1, bB);
                cB = ffma2(w2s[k + 5], hh1, cB);
            }
            float s0 = __fmaf_rn(0.5f, ftanh_hw(hadd2(fadd2(aA, aB))), 0.5f);
            float s1 = __fmaf_rn(0.5f, ftanh_hw(hadd2(fadd2(bA, bB))), 0.5f);
            float tg = ftanh_hw(hadd2(fadd2(cA, cB)));

            float oA = __shfl_sync(0xffffffffu, s0, lane + 20);
            float oB = __shfl_sync(0xffffffffu, s1, lane + 8);
            float o  = (lane < 12) ? oA : oB;

            c  = __fmaf_rn(s1, c, s0 * tg);      // f*c + i*g
            hn = o * ftanh_hw(c);                // o * tanh(c)
        }
        if (ci + 1 < NC) {
            asm volatile("cp.async.wait_group 0;");
            __syncwarp();
            if (ci + 2 < NC) refill(ci + 2, ci & 1);
        }
    }
    if (lane < 20) g_h[b * 20 + lane] = hn;
}

// ---------------------------------------------------------------------------
// Phase 3a: logits + batch-axis softmax. One warp per (k, v); lane handles
// batches (lane, lane+32). Writes probs at out[0..], logits at out[65536..].
// ---------------------------------------------------------------------------
__global__ void __launch_bounds__(256) phase3a(
    const float* __restrict__ dec_W, const float* __restrict__ dec_b,
    float* __restrict__ out)
{
    __shared__ float hs[64 * 20];
    for (int i = threadIdx.x; i < 1280; i += 256) hs[i] = g_h[i];
    __syncthreads();

    int warp = blockIdx.x * 8 + (threadIdx.x >> 5);
    int lane = threadIdx.x & 31;
    int k = warp >> 8, v = warp & 255;

    const float* wrow = dec_W + (k * 256 + v) * 20;
    float w[20];
    #pragma unroll
    for (int e = 0; e < 20; e++) w[e] = __ldg(wrow + e);
    float bb = __ldg(dec_b + k * 256 + v);

    int b0 = lane, b1 = lane + 32;
    float l0 = bb, l1 = bb;
    #pragma unroll
    for (int e = 0; e < 20; e++) {
        l0 += hs[b0 * 20 + e] * w[e];
        l1 += hs[b1 * 20 + e] * w[e];
    }
    out[65536 + (k * 64 + b0) * 256 + v] = l0;
    out[65536 + (k * 64 + b1) * 256 + v] = l1;

    float s0 = l0 / 0.001f, s1 = l1 / 0.001f;   // exact div, mirrors reference
    float m = fmaxf(s0, s1);
    #pragma unroll
    for (int o = 16; o > 0; o >>= 1) m = fmaxf(m, __shfl_xor_sync(0xffffffffu, m, o));
    float p0 = __expf(s0 - m), p1 = __expf(s1 - m);
    float sum = p0 + p1;
    #pragma unroll
    for (int o = 16; o > 0; o >>= 1) sum += __shfl_xor_sync(0xffffffffu, sum, o);
    float inv = __fdividef(1.f, sum);
    out[(k * 64 + b0) * 256 + v] = p0 * inv;
    out[(k * 64 + b1) * 256 + v] = p1 * inv;
}

// ---------------------------------------------------------------------------
// Phase 3b: byte_e = probs @ addr_emb, fe = encoder(byte_e), freq_rec head.
// One CTA per batch element.
// ---------------------------------------------------------------------------
__global__ void __launch_bounds__(128) phase3b(
    const float* __restrict__ addr_emb,
    const float* __restrict__ enc_W, const float* __restrict__ enc_b,
    const float* __restrict__ d1_W, const float* __restrict__ d1_b,
    const float* __restrict__ d2_W, const float* __restrict__ d2_b,
    float* __restrict__ out)
{
    __shared__ float ps[4 * 256];
    __shared__ float xv[80];
    __shared__ float fr_in[60];
    __shared__ float r1[10];

    int b = blockIdx.x, tid = threadIdx.x;
    for (int i = tid; i < 1024; i += 128) {
        int k = i >> 8, v = i & 255;
        ps[i] = out[(k * 64 + b) * 256 + v];
    }
    __syncthreads();

    if (tid < 80) {
        int k = tid / 20, e = tid % 20;
        float acc = 0.f;
        const float* ae = addr_emb + k * 256 * 20 + e;
        const float* pk = ps + k * 256;
        #pragma unroll 8
        for (int v = 0; v < 256; v++) acc += pk[v] * __ldg(ae + v * 20);
        xv[tid] = acc;
    }
    __syncthreads();

    if (tid < 20) {
        float a = enc_b[tid];
        #pragma unroll 8
        for (int e = 0; e < 80; e++) a += xv[e] * enc_W[tid * 80 + e];
        fr_in[tid] = fsig(a);
    }
    if (tid >= 64 && tid < 104) {
        int e = tid - 64;
        fr_in[20 + e] = g_dist[b * 40 + e] * (1.0f / 4096.0f);
    }
    __syncthreads();

    if (tid < 10) {
        float a = d1_b[tid];
        #pragma unroll
        for (int e = 0; e < 60; e++) a += fr_in[e] * d1_W[tid * 60 + e];
        r1[tid] = fmaxf(a, 0.f);
    }
    __syncthreads();

    if (tid < 2) {
        float a = d2_b[tid];
        #pragma unroll
        for (int e = 0; e < 10; e++) a += r1[e] * d2_W[tid * 10 + e];
        out[131072 + tid * 64 + b] = a;
    }
}

// ---------------------------------------------------------------------------
extern "C" void kernel_launch(void* const* d_in, const int* in_sizes, int n_in,
                              void* d_out, int out_size)
{
    const int*   inp      = (const int*)d_in[0];
    const float* h0       = (const float*)d_in[1];
    const float* c0       = (const float*)d_in[2];
    const float* pc_emb   = (const float*)d_in[3];
    const float* addr_emb = (const float*)d_in[4];
    const float* enc_W    = (const float*)d_in[5];
    const float* enc_b    = (const float*)d_in[6];
    const float* W_ih     = (const float*)d_in[7];
    const float* W_hh     = (const float*)d_in[8];
    const float* b_ih     = (const float*)d_in[9];
    const float* b_hh     = (const float*)d_in[10];
    const float* dec_W    = (const float*)d_in[11];
    const float* dec_b    = (const float*)d_in[12];
    const float* d1_W     = (const float*)d_in[13];
    const float* d1_b     = (const float*)d_in[14];
    const float* d2_W     = (const float*)d_in[15];
    const float* d2_b     = (const float*)d_in[16];
    float* out = (float*)d_out;

    initk<<<10, 256>>>();
    prep<<<8, 256>>>(pc_emb, addr_emb, enc_W);
    phase1<<<dim3(16, 64), 256>>>(inp, enc_b, W_ih, b_ih, b_hh);
    phase2<<<64, 32>>>(h0, c0, W_hh);
    phase3a<<<128, 256>>>(dec_W, dec_b, out);
    phase3b<<<64, 128>>>(addr_emb, enc_W, enc_b, d1_W, d1_b, d2_W, d2_b, out);
}

// round 15
// speedup vs baseline: 17.5883x; 1.0438x over previous
#include <cuda_runtime.h>
#include <cstdint>

#define Bk   64
#define Sk   4096
#define EMBk 20
#define HIDk 20
#define VOC  256

// Scratch (static device allocations are allowed; runtime allocs are not)
__device__ float g_xproj[Bk * Sk * 80];   // x@W_ih.T + b (sigmoid rows pre-halved)
__device__ float g_dist[Bk * 40];         // sum over S of emb (for dist_vector)
__device__ float g_h[Bk * 20];            // final LSTM hidden state
__device__ float g_ptab[2 * 4 * 256 * 20];// [tab][bytepos][byteval][o]: emb@W_i^T

typedef unsigned long long u64;

__device__ __forceinline__ float fsig(float x) {
    return __fdividef(1.f, 1.f + __expf(-x));
}

// HW tanh (MUFU.TANH): lat ~16 vs ~44 for exp/div chain
__device__ __forceinline__ float ftanh_hw(float x) {
    float y; asm("tanh.approx.f32 %0, %1;" : "=f"(y) : "f"(x)); return y;
}

// packed f32x2 helpers (Blackwell packed fp32 pipe — PTX-only encodings)
__device__ __forceinline__ u64 pk2(float lo, float hi) {
    u64 r; asm("mov.b64 %0, {%1, %2};" : "=l"(r) : "f"(lo), "f"(hi)); return r;
}
__device__ __forceinline__ u64 ffma2(u64 a, u64 b, u64 c) {
    u64 d; asm("fma.rn.f32x2 %0, %1, %2, %3;" : "=l"(d) : "l"(a), "l"(b), "l"(c));
    return d;
}
__device__ __forceinline__ u64 fadd2(u64 a, u64 b) {
    u64 d; asm("add.rn.f32x2 %0, %1, %2;" : "=l"(d) : "l"(a), "l"(b));
    return d;
}
__device__ __forceinline__ float hadd2(u64 v) {
    float lo, hi; asm("mov.b64 {%0, %1}, %2;" : "=f"(lo), "=f"(hi) : "l"(v));
    return lo + hi;
}

// ---------------------------------------------------------------------------
// init: zero the dist accumulator (must be deterministic per launch)
// ---------------------------------------------------------------------------
__global__ void initk() {
    int i = blockIdx.x * blockDim.x + threadIdx.x;
    if (i < Bk * 40) g_dist[i] = 0.f;
}

// ---------------------------------------------------------------------------
// prep: fold the encoder weight into the byte-embedding tables.
// g_ptab[t][i][v][o] = sum_k emb_t[i*256+v][k] * enc_W[o][i*20+k]
// ---------------------------------------------------------------------------
__global__ void __launch_bounds__(256) prep(
    const float* __restrict__ pc_emb, const float* __restrict__ addr_emb,
    const float* __restrict__ enc_W)
{
    int r = blockIdx.x * 256 + threadIdx.x;      // 0..2047
    int tab = r >> 10;
    int rem = r & 1023;
    int i = rem >> 8;                            // byte position 0..3
    const float* emb = (tab ? addr_emb : pc_emb) + rem * 20;
    float e[20];
    #pragma unroll
    for (int k = 0; k < 20; k++) e[k] = __ldg(emb + k);
    float* outp = g_ptab + r * 20;
    #pragma unroll 4
    for (int o = 0; o < 20; o++) {
        const float* w = enc_W + o * 80 + i * 20;
        float a = 0.f;
        #pragma unroll
        for (int k = 0; k < 20; k++) a += e[k] * __ldg(w + k);
        outp[o] = a;
    }
}

// ---------------------------------------------------------------------------
// encoder helper: emb[40] for one (pc, addr) pair via pre-projected tables
// ---------------------------------------------------------------------------
__device__ __forceinline__ void enc_pos(int2 pv, const float* sbe, float* emb) {
    #pragma unroll
    for (int p = 0; p < 2; p++) {
        unsigned val = (unsigned)(p ? pv.y : pv.x);
        const float* ptab = g_ptab + p * (4 * 256 * 20);
        float4 a0, a1, a2, a3, a4;
        {
            unsigned byt = (val >> 24) & 0xFFu;
            const float4* row = (const float4*)(ptab + (int)byt * 20);
            a0 = __ldg(row);     a1 = __ldg(row + 1); a2 = __ldg(row + 2);
            a3 = __ldg(row + 3); a4 = __ldg(row + 4);
        }
        #pragma unroll
        for (int i = 1; i < 4; i++) {
            unsigned byt = (val >> (24 - 8 * i)) & 0xFFu;
            const float4* row =
                (const float4*)(ptab + (i * 256 + (int)byt) * 20);
            float4 g0 = __ldg(row),     g1 = __ldg(row + 1),
                   g2 = __ldg(row + 2), g3 = __ldg(row + 3),
                   g4 = __ldg(row + 4);
            a0.x += g0.x; a0.y += g0.y; a0.z += g0.z; a0.w += g0.w;
            a1.x += g1.x; a1.y += g1.y; a1.z += g1.z; a1.w += g1.w;
            a2.x += g2.x; a2.y += g2.y; a2.z += g2.z; a2.w += g2.w;
            a3.x += g3.x; a3.y += g3.y; a3.z += g3.z; a3.w += g3.w;
            a4.x += g4.x; a4.y += g4.y; a4.z += g4.z; a4.w += g4.w;
        }
        float acc[20];
        acc[0]  = a0.x; acc[1]  = a0.y; acc[2]  = a0.z; acc[3]  = a0.w;
        acc[4]  = a1.x; acc[5]  = a1.y; acc[6]  = a1.z; acc[7]  = a1.w;
        acc[8]  = a2.x; acc[9]  = a2.y; acc[10] = a2.z; acc[11] = a2.w;
        acc[12] = a3.x; acc[13] = a3.y; acc[14] = a3.z; acc[15] = a3.w;
        acc[16] = a4.x; acc[17] = a4.y; acc[18] = a4.z; acc[19] = a4.w;
        #pragma unroll
        for (int o = 0; o < 20; o++)
            emb[p * 20 + o] = fsig(acc[o] + sbe[o]);
    }
}

// ---------------------------------------------------------------------------
// Phase 1: byte-embedding via pre-projected tables + x-projection. Each
// thread handles TWO positions (s, s+256): every weight LDS in the x-proj
// inner loop feeds two ffma2, halving LDS issue per position. Sigmoid-gate
// rows (j<40 or j>=60) of the projection PRE-SCALED by 0.5. grid (8,64).
// ---------------------------------------------------------------------------
__global__ void __launch_bounds__(256) phase1(
    const int* __restrict__ inp,
    const float* __restrict__ enc_b,
    const float* __restrict__ W_ih, const float* __restrict__ b_ih,
    const float* __restrict__ b_hh)
{
    __shared__ __align__(16) float sWih[80 * 40];
    __shared__ float sbe[20];
    __shared__ float sbs[80];
    __shared__ float ssum[40];

    int tid = threadIdx.x;
    for (int i = tid; i < 3200; i += 256) {
        int row = i / 40;
        float sc = (row >= 40 && row < 60) ? 1.f : 0.5f;
        sWih[i] = W_ih[i] * sc;
    }
    if (tid < 20) sbe[tid] = enc_b[tid];
    if (tid < 80) {
        float sc = (tid >= 40 && tid < 60) ? 1.f : 0.5f;
        sbs[tid] = (b_ih[tid] + b_hh[tid]) * sc;
    }
    if (tid < 40) ssum[tid] = 0.f;
    __syncthreads();

    int b = blockIdx.y;
    int s0 = blockIdx.x * 512 + tid;
    int s1 = s0 + 256;
    int2 pv0 = ((const int2*)inp)[b * Sk + s0];
    int2 pv1 = ((const int2*)inp)[b * Sk + s1];

    float embA[40], embB[40];
    enc_pos(pv0, sbe, embA);
    enc_pos(pv1, sbe, embB);

    // dist_vector accumulation (both positions folded before packing)
    #pragma unroll
    for (int e = 0; e < 40; e++) {
        float v2 = embA[e] + embB[e];
        v2 += __shfl_xor_sync(0xffffffffu, v2, 16);
        v2 += __shfl_xor_sync(0xffffffffu, v2, 8);
        v2 += __shfl_xor_sync(0xffffffffu, v2, 4);
        v2 += __shfl_xor_sync(0xffffffffu, v2, 2);
        v2 += __shfl_xor_sync(0xffffffffu, v2, 1);
        if ((tid & 31) == 0) atomicAdd(&ssum[e], v2);
    }

    // x-projection for BOTH positions: weights loaded once, used twice.
    {
        u64 xa[20], xb[20];
        #pragma unroll
        for (int m = 0; m < 20; m++) {
            xa[m] = pk2(embA[2 * m], embA[2 * m + 1]);
            xb[m] = pk2(embB[2 * m], embB[2 * m + 1]);
        }

        float4* outA = (float4*)g_xproj + (b * Sk + s0) * 20;
        float4* outB = (float4*)g_xproj + (b * Sk + s1) * 20;
        #pragma unroll 1
        for (int jq = 0; jq < 20; jq++) {
            float bs0 = sbs[jq * 4 + 0], bs1 = sbs[jq * 4 + 1];
            float bs2 = sbs[jq * 4 + 2], bs3 = sbs[jq * 4 + 3];
            u64 A0 = pk2(bs0, 0.f), A1 = pk2(bs1, 0.f);
            u64 A2 = pk2(bs2, 0.f), A3 = pk2(bs3, 0.f);
            u64 B0 = pk2(bs0, 0.f), B1 = pk2(bs1, 0.f);
            u64 B2 = pk2(bs2, 0.f), B3 = pk2(bs3, 0.f);
            const u64* w0 = (const u64*)(sWih + (jq * 4 + 0) * 40);
            const u64* w1 = (const u64*)(sWih + (jq * 4 + 1) * 40);
            const u64* w2 = (const u64*)(sWih + (jq * 4 + 2) * 40);
            const u64* w3 = (const u64*)(sWih + (jq * 4 + 3) * 40);
            #pragma unroll
            for (int m = 0; m < 20; m++) {
                u64 wm0 = w0[m], wm1 = w1[m], wm2 = w2[m], wm3 = w3[m];
                u64 xam = xa[m], xbm = xb[m];
                A0 = ffma2(wm0, xam, A0);  B0 = ffma2(wm0, xbm, B0);
                A1 = ffma2(wm1, xam, A1);  B1 = ffma2(wm1, xbm, B1);
                A2 = ffma2(wm2, xam, A2);  B2 = ffma2(wm2, xbm, B2);
                A3 = ffma2(wm3, xam, A3);  B3 = ffma2(wm3, xbm, B3);
            }
            outA[jq] = make_float4(hadd2(A0), hadd2(A1), hadd2(A2), hadd2(A3));
            outB[jq] = make_float4(hadd2(B0), hadd2(B1), hadd2(B2), hadd2(B3));
        }
    }

    __syncthreads();
    if (tid < 40) atomicAdd(&g_dist[b * 40 + tid], ssum[tid]);
}

// ---------------------------------------------------------------------------
// Phase 2: sequential LSTM, ONE WARP per batch element — EXACT round-7 body
// (the measured optimum; all pairing/exchange restructurings lost).
// Slot mapping (3 dot slots cover all 80 gates):
//   slot0: lanes 0-19 -> i_l      lanes 20-31 -> o_{l-20} (rows 60-71)
//   slot1: lanes 0-19 -> f_l      lanes 20-27 -> o_{l-8}  (rows 72-79)
//   slot2: lanes 0-19 -> g_l      lanes 20-31 -> dummy (row 79)
// Inline SHFL h-broadcast overlapping the 2-way-tree fma.f32x2 chains;
// MUFU.TANH activations; sigmoid 0.5 pre-folded into W_hh rows and g_xproj.
// ---------------------------------------------------------------------------
__global__ void __launch_bounds__(32) phase2(
    const float* __restrict__ h0, const float* __restrict__ c0,
    const float* __restrict__ W_hh)
{
    __shared__ __align__(16) float xs[2][32 * 80];
    const int lane = threadIdx.x;
    const int b = blockIdx.x;

    const int r0 = (lane < 20) ? lane      : 40 + lane;               // 60..71
    const int r1 = (lane < 20) ? 20 + lane : (lane < 28 ? 52 + lane : 79);
    const int r2 = (lane < 20) ? 40 + lane : 79;

    // slot0/slot1 rows are ALL sigmoid rows -> pre-scale by 0.5 (tanh identity)
    u64 w0[10], w1[10], w2s[10];
    #pragma unroll
    for (int k = 0; k < 10; k++) {
        float2 a;
        a = ((const float2*)(W_hh + r0 * 20))[k]; w0[k]  = pk2(0.5f * a.x, 0.5f * a.y);
        a = ((const float2*)(W_hh + r1 * 20))[k]; w1[k]  = pk2(0.5f * a.x, 0.5f * a.y);
        a = ((const float2*)(W_hh + r2 * 20))[k]; w2s[k] = pk2(a.x, a.y);
    }
    float hn = (lane < 20) ? h0[b * 20 + lane] : 0.f;
    float c  = (lane < 20) ? c0[b * 20 + lane] : 0.f;

    const float4* src = (const float4*)g_xproj + (size_t)b * (Sk * 20);
    unsigned sm0 = (unsigned)__cvta_generic_to_shared(&xs[0][0]);

    auto refill = [&](int chunk, int buf) {
        unsigned d = sm0 + (unsigned)buf * (2560u * 4u);
        const float4* s = src + chunk * 640;
        #pragma unroll
        for (int q = 0; q < 20; q++) {
            unsigned da = d + (unsigned)(lane + 32 * q) * 16u;
            const float4* sa = s + lane + 32 * q;
            asm volatile("cp.async.cg.shared.global [%0], [%1], 16;"
                         :: "r"(da), "l"(sa));
        }
        asm volatile("cp.async.commit_group;");
    };

    refill(0, 0);
    refill(1, 1);
    asm volatile("cp.async.wait_group 1;");
    __syncwarp();

    const u64 Z2 = pk2(0.f, 0.f);
    const int NC = Sk / 32;
    for (int ci = 0; ci < NC; ci++) {
        const float* xb = &xs[ci & 1][0];
        #pragma unroll 2
        for (int t = 0; t < 32; t++) {
            const float* xt = xb + t * 80;
            // hoist x loads: LDS latency hides under the shfl stream
            float x0 = xt[r0], x1 = xt[r1], x2 = xt[r2];
            u64 aA = pk2(x0, 0.f), aB = Z2;
            u64 bA = pk2(x1, 0.f), bB = Z2;
            u64 cA = pk2(x2, 0.f), cB = Z2;
            // inline h-broadcast: shfl latency overlaps the fma.f32x2 chains.
            // 2-way tree per slot: k=0..4 -> *A, k=5..9 -> *B (independent).
            #pragma unroll
            for (int k = 0; k < 5; k++) {
                float lo0 = __shfl_sync(0xffffffffu, hn, 2 * k);
                float hi0 = __shfl_sync(0xffffffffu, hn, 2 * k + 1);
                u64 hh0 = pk2(lo0, hi0);
                float lo1 = __shfl_sync(0xffffffffu, hn, 2 * k + 10);
                float hi1 = __shfl_sync(0xffffffffu, hn, 2 * k + 11);
                u64 hh1 = pk2(lo1, hi1);
                aA = ffma2(w0[k],      hh0, aA);
                bA = ffma2(w1[k],      hh0, bA);
                cA = ffma2(w2s[k],     hh0, cA);
                aB = ffma2(w0[k + 5],  hh1, aB);
                bB = ffma2(w1[k + 5],  hh1, bB);
                cB = ffma2(w2s[k + 5], hh1, cB);
            }
            float s0 = __fmaf_rn(0.5f, ftanh_hw(hadd2(fadd2(aA, aB))), 0.5f);
            float s1 = __fmaf_rn(0.5f, ftanh_hw(hadd2(fadd2(bA, bB))), 0.5f);
            float tg = ftanh_hw(hadd2(fadd2(cA, cB)));

            float oA = __shfl_sync(0xffffffffu, s0, lane + 20);
            float oB = __shfl_sync(0xffffffffu, s1, lane + 8);
            float o  = (lane < 12) ? oA : oB;

            c  = __fmaf_rn(s1, c, s0 * tg);      // f*c + i*g
            hn = o * ftanh_hw(c);                // o * tanh(c)
        }
        if (ci + 1 < NC) {
            asm volatile("cp.async.wait_group 0;");
            __syncwarp();
            if (ci + 2 < NC) refill(ci + 2, ci & 1);
        }
    }
    if (lane < 20) g_h[b * 20 + lane] = hn;
}

// ---------------------------------------------------------------------------
// Phase 3a: logits + batch-axis softmax. One warp per (k, v); lane handles
// batches (lane, lane+32). Writes probs at out[0..], logits at out[65536..].
// ---------------------------------------------------------------------------
__global__ void __launch_bounds__(256) phase3a(
    const float* __restrict__ dec_W, const float* __restrict__ dec_b,
    float* __restrict__ out)
{
    __shared__ float hs[64 * 20];
    for (int i = threadIdx.x; i < 1280; i += 256) hs[i] = g_h[i];
    __syncthreads();

    int warp = blockIdx.x * 8 + (threadIdx.x >> 5);
    int lane = threadIdx.x & 31;
    int k = warp >> 8, v = warp & 255;

    const float* wrow = dec_W + (k * 256 + v) * 20;
    float w[20];
    #pragma unroll
    for (int e = 0; e < 20; e++) w[e] = __ldg(wrow + e);
    float bb = __ldg(dec_b + k * 256 + v);

    int b0 = lane, b1 = lane + 32;
    float l0 = bb, l1 = bb;
    #pragma unroll
    for (int e = 0; e < 20; e++) {
        l0 += hs[b0 * 20 + e] * w[e];
        l1 += hs[b1 * 20 + e] * w[e];
    }
    out[65536 + (k * 64 + b0) * 256 + v] = l0;
    out[65536 + (k * 64 + b1) * 256 + v] = l1;

    float s0 = l0 / 0.001f, s1 = l1 / 0.001f;   // exact div, mirrors reference
    float m = fmaxf(s0, s1);
    #pragma unroll
    for (int o = 16; o > 0; o >>= 1) m = fmaxf(m, __shfl_xor_sync(0xffffffffu, m, o));
    float p0 = __expf(s0 - m), p1 = __expf(s1 - m);
    float sum = p0 + p1;
    #pragma unroll
    for (int o = 16; o > 0; o >>= 1) sum += __shfl_xor_sync(0xffffffffu, sum, o);
    float inv = __fdividef(1.f, sum);
    out[(k * 64 + b0) * 256 + v] = p0 * inv;
    out[(k * 64 + b1) * 256 + v] = p1 * inv;
}

// ---------------------------------------------------------------------------
// Phase 3b: byte_e = probs @ addr_emb, fe = encoder(byte_e), freq_rec head.
// One CTA per batch element.
// ---------------------------------------------------------------------------
__global__ void __launch_bounds__(128) phase3b(
    const float* __restrict__ addr_emb,
    const float* __restrict__ enc_W, const float* __restrict__ enc_b,
    const float* __restrict__ d1_W, const float* __restrict__ d1_b,
    const float* __restrict__ d2_W, const float* __restrict__ d2_b,
    float* __restrict__ out)
{
    __shared__ float ps[4 * 256];
    __shared__ float xv[80];
    __shared__ float fr_in[60];
    __shared__ float r1[10];

    int b = blockIdx.x, tid = threadIdx.x;
    for (int i = tid; i < 1024; i += 128) {
        int k = i >> 8, v = i & 255;
        ps[i] = out[(k * 64 + b) * 256 + v];
    }
    __syncthreads();

    if (tid < 80) {
        int k = tid / 20, e = tid % 20;
        float acc = 0.f;
        const float* ae = addr_emb + k * 256 * 20 + e;
        const float* pk = ps + k * 256;
        #pragma unroll 8
        for (int v = 0; v < 256; v++) acc += pk[v] * __ldg(ae + v * 20);
        xv[tid] = acc;
    }
    __syncthreads();

    if (tid < 20) {
        float a = enc_b[tid];
        #pragma unroll 8
        for (int e = 0; e < 80; e++) a += xv[e] * enc_W[tid * 80 + e];
        fr_in[tid] = fsig(a);
    }
    if (tid >= 64 && tid < 104) {
        int e = tid - 64;
        fr_in[20 + e] = g_dist[b * 40 + e] * (1.0f / 4096.0f);
    }
    __syncthreads();

    if (tid < 10) {
        float a = d1_b[tid];
        #pragma unroll
        for (int e = 0; e < 60; e++) a += fr_in[e] * d1_W[tid * 60 + e];
        r1[tid] = fmaxf(a, 0.f);
    }
    __syncthreads();

    if (tid < 2) {
        float a = d2_b[tid];
        #pragma unroll
        for (int e = 0; e < 10; e++) a += r1[e] * d2_W[tid * 10 + e];
        out[131072 + tid * 64 + b] = a;
    }
}

// ---------------------------------------------------------------------------
extern "C" void kernel_launch(void* const* d_in, const int* in_sizes, int n_in,
                              void* d_out, int out_size)
{
    const int*   inp      = (const int*)d_in[0];
    const float* h0       = (const float*)d_in[1];
    const float* c0       = (const float*)d_in[2];
    const float* pc_emb   = (const float*)d_in[3];
    const float* addr_emb = (const float*)d_in[4];
    const float* enc_W    = (const float*)d_in[5];
    const float* enc_b    = (const float*)d_in[6];
    const float* W_ih     = (const float*)d_in[7];
    const float* W_hh     = (const float*)d_in[8];
    const float* b_ih     = (const float*)d_in[9];
    const float* b_hh     = (const float*)d_in[10];
    const float* dec_W    = (const float*)d_in[11];
    const float* dec_b    = (const float*)d_in[12];
    const float* d1_W     = (const float*)d_in[13];
    const float* d1_b     = (const float*)d_in[14];
    const float* d2_W     = (const float*)d_in[15];
    const float* d2_b     = (const float*)d_in[16];
    float* out = (float*)d_out;

    initk<<<10, 256>>>();
    prep<<<8, 256>>>(pc_emb, addr_emb, enc_W);
    phase1<<<dim3(8, 64), 256>>>(inp, enc_b, W_ih, b_ih, b_hh);
    phase2<<<64, 32>>>(h0, c0, W_hh);
    phase3a<<<128, 256>>>(dec_W, dec_b, out);
    phase3b<<<64, 128>>>(addr_emb, enc_W, enc_b, d1_W, d1_b, d2_W, d2_b, out);
}

// round 16
// speedup vs baseline: 18.2066x; 1.0352x over previous
#include <cuda_runtime.h>
#include <cstdint>

#define Bk   64
#define Sk   4096
#define EMBk 20
#define HIDk 20
#define VOC  256

// Scratch (static device allocations are allowed; runtime allocs are not)
__device__ float g_xproj[Bk * Sk * 80];   // x@W_ih.T + b (sigmoid rows pre-halved)
__device__ float g_dist[Bk * 40];         // sum over S of emb (for dist_vector)
__device__ float g_h[Bk * 20];            // final LSTM hidden state
__device__ float g_ptab[2 * 4 * 256 * 20];// [tab][bytepos][byteval][o]: emb@W_i^T

typedef unsigned long long u64;

__device__ __forceinline__ float fsig(float x) {
    return __fdividef(1.f, 1.f + __expf(-x));
}

// HW tanh (MUFU.TANH): lat ~16 vs ~44 for exp/div chain
__device__ __forceinline__ float ftanh_hw(float x) {
    float y; asm("tanh.approx.f32 %0, %1;" : "=f"(y) : "f"(x)); return y;
}

// packed f32x2 helpers (Blackwell packed fp32 pipe — PTX-only encodings)
__device__ __forceinline__ u64 pk2(float lo, float hi) {
    u64 r; asm("mov.b64 %0, {%1, %2};" : "=l"(r) : "f"(lo), "f"(hi)); return r;
}
__device__ __forceinline__ u64 ffma2(u64 a, u64 b, u64 c) {
    u64 d; asm("fma.rn.f32x2 %0, %1, %2, %3;" : "=l"(d) : "l"(a), "l"(b), "l"(c));
    return d;
}
__device__ __forceinline__ u64 fadd2(u64 a, u64 b) {
    u64 d; asm("add.rn.f32x2 %0, %1, %2;" : "=l"(d) : "l"(a), "l"(b));
    return d;
}
__device__ __forceinline__ float hadd2(u64 v) {
    float lo, hi; asm("mov.b64 {%0, %1}, %2;" : "=f"(lo), "=f"(hi) : "l"(v));
    return lo + hi;
}

// ---------------------------------------------------------------------------
// init: zero the dist accumulator (must be deterministic per launch)
// ---------------------------------------------------------------------------
__global__ void initk() {
    int i = blockIdx.x * blockDim.x + threadIdx.x;
    if (i < Bk * 40) g_dist[i] = 0.f;
}

// ---------------------------------------------------------------------------
// prep: fold the encoder weight into the byte-embedding tables.
// g_ptab[t][i][v][o] = sum_k emb_t[i*256+v][k] * enc_W[o][i*20+k]
// ---------------------------------------------------------------------------
__global__ void __launch_bounds__(256) prep(
    const float* __restrict__ pc_emb, const float* __restrict__ addr_emb,
    const float* __restrict__ enc_W)
{
    int r = blockIdx.x * 256 + threadIdx.x;      // 0..2047
    int tab = r >> 10;
    int rem = r & 1023;
    int i = rem >> 8;                            // byte position 0..3
    const float* emb = (tab ? addr_emb : pc_emb) + rem * 20;
    float e[20];
    #pragma unroll
    for (int k = 0; k < 20; k++) e[k] = __ldg(emb + k);
    float* outp = g_ptab + r * 20;
    #pragma unroll 4
    for (int o = 0; o < 20; o++) {
        const float* w = enc_W + o * 80 + i * 20;
        float a = 0.f;
        #pragma unroll
        for (int k = 0; k < 20; k++) a += e[k] * __ldg(w + k);
        outp[o] = a;
    }
}

// ---------------------------------------------------------------------------
// encoder helper: emb[40] for one (pc, addr) pair via pre-projected tables
// ---------------------------------------------------------------------------
__device__ __forceinline__ void enc_pos(int2 pv, const float* sbe, float* emb) {
    #pragma unroll
    for (int p = 0; p < 2; p++) {
        unsigned val = (unsigned)(p ? pv.y : pv.x);
        const float* ptab = g_ptab + p * (4 * 256 * 20);
        float4 a0, a1, a2, a3, a4;
        {
            unsigned byt = (val >> 24) & 0xFFu;
            const float4* row = (const float4*)(ptab + (int)byt * 20);
            a0 = __ldg(row);     a1 = __ldg(row + 1); a2 = __ldg(row + 2);
            a3 = __ldg(row + 3); a4 = __ldg(row + 4);
        }
        #pragma unroll
        for (int i = 1; i < 4; i++) {
            unsigned byt = (val >> (24 - 8 * i)) & 0xFFu;
            const float4* row =
                (const float4*)(ptab + (i * 256 + (int)byt) * 20);
            float4 g0 = __ldg(row),     g1 = __ldg(row + 1),
                   g2 = __ldg(row + 2), g3 = __ldg(row + 3),
                   g4 = __ldg(row + 4);
            a0.x += g0.x; a0.y += g0.y; a0.z += g0.z; a0.w += g0.w;
            a1.x += g1.x; a1.y += g1.y; a1.z += g1.z; a1.w += g1.w;
            a2.x += g2.x; a2.y += g2.y; a2.z += g2.z; a2.w += g2.w;
            a3.x += g3.x; a3.y += g3.y; a3.z += g3.z; a3.w += g3.w;
            a4.x += g4.x; a4.y += g4.y; a4.z += g4.z; a4.w += g4.w;
        }
        float acc[20];
        acc[0]  = a0.x; acc[1]  = a0.y; acc[2]  = a0.z; acc[3]  = a0.w;
        acc[4]  = a1.x; acc[5]  = a1.y; acc[6]  = a1.z; acc[7]  = a1.w;
        acc[8]  = a2.x; acc[9]  = a2.y; acc[10] = a2.z; acc[11] = a2.w;
        acc[12] = a3.x; acc[13] = a3.y; acc[14] = a3.z; acc[15] = a3.w;
        acc[16] = a4.x; acc[17] = a4.y; acc[18] = a4.z; acc[19] = a4.w;
        #pragma unroll
        for (int o = 0; o < 20; o++)
            emb[p * 20 + o] = fsig(acc[o] + sbe[o]);
    }
}

// ---------------------------------------------------------------------------
// Phase 1: byte-embedding via pre-projected tables + x-projection. Each
// thread handles TWO positions (s, s+256): every weight LDS in the x-proj
// inner loop feeds two ffma2, halving LDS issue per position. Sigmoid-gate
// rows (j<40 or j>=60) of the projection PRE-SCALED by 0.5. grid (8,64).
// ---------------------------------------------------------------------------
__global__ void __launch_bounds__(256) phase1(
    const int* __restrict__ inp,
    const float* __restrict__ enc_b,
    const float* __restrict__ W_ih, const float* __restrict__ b_ih,
    const float* __restrict__ b_hh)
{
    __shared__ __align__(16) float sWih[80 * 40];
    __shared__ float sbe[20];
    __shared__ float sbs[80];
    __shared__ float ssum[40];

    int tid = threadIdx.x;
    for (int i = tid; i < 3200; i += 256) {
        int row = i / 40;
        float sc = (row >= 40 && row < 60) ? 1.f : 0.5f;
        sWih[i] = W_ih[i] * sc;
    }
    if (tid < 20) sbe[tid] = enc_b[tid];
    if (tid < 80) {
        float sc = (tid >= 40 && tid < 60) ? 1.f : 0.5f;
        sbs[tid] = (b_ih[tid] + b_hh[tid]) * sc;
    }
    if (tid < 40) ssum[tid] = 0.f;
    __syncthreads();

    int b = blockIdx.y;
    int s0 = blockIdx.x * 512 + tid;
    int s1 = s0 + 256;
    int2 pv0 = ((const int2*)inp)[b * Sk + s0];
    int2 pv1 = ((const int2*)inp)[b * Sk + s1];

    float embA[40], embB[40];
    enc_pos(pv0, sbe, embA);
    enc_pos(pv1, sbe, embB);

    // dist_vector accumulation (both positions folded before packing)
    #pragma unroll
    for (int e = 0; e < 40; e++) {
        float v2 = embA[e] + embB[e];
        v2 += __shfl_xor_sync(0xffffffffu, v2, 16);
        v2 += __shfl_xor_sync(0xffffffffu, v2, 8);
        v2 += __shfl_xor_sync(0xffffffffu, v2, 4);
        v2 += __shfl_xor_sync(0xffffffffu, v2, 2);
        v2 += __shfl_xor_sync(0xffffffffu, v2, 1);
        if ((tid & 31) == 0) atomicAdd(&ssum[e], v2);
    }

    // x-projection for BOTH positions: weights loaded once, used twice.
    {
        u64 xa[20], xb[20];
        #pragma unroll
        for (int m = 0; m < 20; m++) {
            xa[m] = pk2(embA[2 * m], embA[2 * m + 1]);
            xb[m] = pk2(embB[2 * m], embB[2 * m + 1]);
        }

        float4* outA = (float4*)g_xproj + (b * Sk + s0) * 20;
        float4* outB = (float4*)g_xproj + (b * Sk + s1) * 20;
        #pragma unroll 1
        for (int jq = 0; jq < 20; jq++) {
            float bs0 = sbs[jq * 4 + 0], bs1 = sbs[jq * 4 + 1];
            float bs2 = sbs[jq * 4 + 2], bs3 = sbs[jq * 4 + 3];
            u64 A0 = pk2(bs0, 0.f), A1 = pk2(bs1, 0.f);
            u64 A2 = pk2(bs2, 0.f), A3 = pk2(bs3, 0.f);
            u64 B0 = pk2(bs0, 0.f), B1 = pk2(bs1, 0.f);
            u64 B2 = pk2(bs2, 0.f), B3 = pk2(bs3, 0.f);
            const u64* w0 = (const u64*)(sWih + (jq * 4 + 0) * 40);
            const u64* w1 = (const u64*)(sWih + (jq * 4 + 1) * 40);
            const u64* w2 = (const u64*)(sWih + (jq * 4 + 2) * 40);
            const u64* w3 = (const u64*)(sWih + (jq * 4 + 3) * 40);
            #pragma unroll
            for (int m = 0; m < 20; m++) {
                u64 wm0 = w0[m], wm1 = w1[m], wm2 = w2[m], wm3 = w3[m];
                u64 xam = xa[m], xbm = xb[m];
                A0 = ffma2(wm0, xam, A0);  B0 = ffma2(wm0, xbm, B0);
                A1 = ffma2(wm1, xam, A1);  B1 = ffma2(wm1, xbm, B1);
                A2 = ffma2(wm2, xam, A2);  B2 = ffma2(wm2, xbm, B2);
                A3 = ffma2(wm3, xam, A3);  B3 = ffma2(wm3, xbm, B3);
            }
            outA[jq] = make_float4(hadd2(A0), hadd2(A1), hadd2(A2), hadd2(A3));
            outB[jq] = make_float4(hadd2(B0), hadd2(B1), hadd2(B2), hadd2(B3));
        }
    }

    __syncthreads();
    if (tid < 40) atomicAdd(&g_dist[b * 40 + tid], ssum[tid]);
}

// ---------------------------------------------------------------------------
// Phase 2: sequential LSTM, ONE WARP per batch element — EXACT round-7 body
// (the measured optimum; all pairing/exchange restructurings lost).
// ---------------------------------------------------------------------------
__global__ void __launch_bounds__(32) phase2(
    const float* __restrict__ h0, const float* __restrict__ c0,
    const float* __restrict__ W_hh)
{
    __shared__ __align__(16) float xs[2][32 * 80];
    const int lane = threadIdx.x;
    const int b = blockIdx.x;

    const int r0 = (lane < 20) ? lane      : 40 + lane;               // 60..71
    const int r1 = (lane < 20) ? 20 + lane : (lane < 28 ? 52 + lane : 79);
    const int r2 = (lane < 20) ? 40 + lane : 79;

    // slot0/slot1 rows are ALL sigmoid rows -> pre-scale by 0.5 (tanh identity)
    u64 w0[10], w1[10], w2s[10];
    #pragma unroll
    for (int k = 0; k < 10; k++) {
        float2 a;
        a = ((const float2*)(W_hh + r0 * 20))[k]; w0[k]  = pk2(0.5f * a.x, 0.5f * a.y);
        a = ((const float2*)(W_hh + r1 * 20))[k]; w1[k]  = pk2(0.5f * a.x, 0.5f * a.y);
        a = ((const float2*)(W_hh + r2 * 20))[k]; w2s[k] = pk2(a.x, a.y);
    }
    float hn = (lane < 20) ? h0[b * 20 + lane] : 0.f;
    float c  = (lane < 20) ? c0[b * 20 + lane] : 0.f;

    const float4* src = (const float4*)g_xproj + (size_t)b * (Sk * 20);
    unsigned sm0 = (unsigned)__cvta_generic_to_shared(&xs[0][0]);

    auto refill = [&](int chunk, int buf) {
        unsigned d = sm0 + (unsigned)buf * (2560u * 4u);
        const float4* s = src + chunk * 640;
        #pragma unroll
        for (int q = 0; q < 20; q++) {
            unsigned da = d + (unsigned)(lane + 32 * q) * 16u;
            const float4* sa = s + lane + 32 * q;
            asm volatile("cp.async.cg.shared.global [%0], [%1], 16;"
                         :: "r"(da), "l"(sa));
        }
        asm volatile("cp.async.commit_group;");
    };

    refill(0, 0);
    refill(1, 1);
    asm volatile("cp.async.wait_group 1;");
    __syncwarp();

    const u64 Z2 = pk2(0.f, 0.f);
    const int NC = Sk / 32;
    for (int ci = 0; ci < NC; ci++) {
        const float* xb = &xs[ci & 1][0];
        #pragma unroll 2
        for (int t = 0; t < 32; t++) {
            const float* xt = xb + t * 80;
            float x0 = xt[r0], x1 = xt[r1], x2 = xt[r2];
            u64 aA = pk2(x0, 0.f), aB = Z2;
            u64 bA = pk2(x1, 0.f), bB = Z2;
            u64 cA = pk2(x2, 0.f), cB = Z2;
            #pragma unroll
            for (int k = 0; k < 5; k++) {
                float lo0 = __shfl_sync(0xffffffffu, hn, 2 * k);
                float hi0 = __shfl_sync(0xffffffffu, hn, 2 * k + 1);
                u64 hh0 = pk2(lo0, hi0);
                float lo1 = __shfl_sync(0xffffffffu, hn, 2 * k + 10);
                float hi1 = __shfl_sync(0xffffffffu, hn, 2 * k + 11);
                u64 hh1 = pk2(lo1, hi1);
                aA = ffma2(w0[k],      hh0, aA);
                bA = ffma2(w1[k],      hh0, bA);
                cA = ffma2(w2s[k],     hh0, cA);
                aB = ffma2(w0[k + 5],  hh1, aB);
                bB = ffma2(w1[k + 5],  hh1, bB);
                cB = ffma2(w2s[k + 5], hh1, cB);
            }
            float s0 = __fmaf_rn(0.5f, ftanh_hw(hadd2(fadd2(aA, aB))), 0.5f);
            float s1 = __fmaf_rn(0.5f, ftanh_hw(hadd2(fadd2(bA, bB))), 0.5f);
            float tg = ftanh_hw(hadd2(fadd2(cA, cB)));

            float oA = __shfl_sync(0xffffffffu, s0, lane + 20);
            float oB = __shfl_sync(0xffffffffu, s1, lane + 8);
            float o  = (lane < 12) ? oA : oB;

            c  = __fmaf_rn(s1, c, s0 * tg);      // f*c + i*g
            hn = o * ftanh_hw(c);                // o * tanh(c)
        }
        if (ci + 1 < NC) {
            asm volatile("cp.async.wait_group 0;");
            __syncwarp();
            if (ci + 2 < NC) refill(ci + 2, ci & 1);
        }
    }
    if (lane < 20) g_h[b * 20 + lane] = hn;
}

// ---------------------------------------------------------------------------
// Phase 3a: logits + batch-axis softmax. One warp per (k, v); lane handles
// batches (lane, lane+32). Writes probs at out[0..], logits at out[65536..].
// ---------------------------------------------------------------------------
__global__ void __launch_bounds__(256) phase3a(
    const float* __restrict__ dec_W, const float* __restrict__ dec_b,
    float* __restrict__ out)
{
    __shared__ float hs[64 * 20];
    for (int i = threadIdx.x; i < 1280; i += 256) hs[i] = g_h[i];
    __syncthreads();

    int warp = blockIdx.x * 8 + (threadIdx.x >> 5);
    int lane = threadIdx.x & 31;
    int k = warp >> 8, v = warp & 255;

    const float* wrow = dec_W + (k * 256 + v) * 20;
    float w[20];
    #pragma unroll
    for (int e = 0; e < 20; e++) w[e] = __ldg(wrow + e);
    float bb = __ldg(dec_b + k * 256 + v);

    int b0 = lane, b1 = lane + 32;
    float l0 = bb, l1 = bb;
    #pragma unroll
    for (int e = 0; e < 20; e++) {
        l0 += hs[b0 * 20 + e] * w[e];
        l1 += hs[b1 * 20 + e] * w[e];
    }
    out[65536 + (k * 64 + b0) * 256 + v] = l0;
    out[65536 + (k * 64 + b1) * 256 + v] = l1;

    float s0 = l0 / 0.001f, s1 = l1 / 0.001f;   // exact div, mirrors reference
    float m = fmaxf(s0, s1);
    #pragma unroll
    for (int o = 16; o > 0; o >>= 1) m = fmaxf(m, __shfl_xor_sync(0xffffffffu, m, o));
    float p0 = __expf(s0 - m), p1 = __expf(s1 - m);
    float sum = p0 + p1;
    #pragma unroll
    for (int o = 16; o > 0; o >>= 1) sum += __shfl_xor_sync(0xffffffffu, sum, o);
    float inv = __fdividef(1.f, sum);
    out[(k * 64 + b0) * 256 + v] = p0 * inv;
    out[(k * 64 + b1) * 256 + v] = p1 * inv;
}

// ---------------------------------------------------------------------------
// Phase 3b (REWRITTEN): fe_logit[o] = sum_{k,v} probs[k][v] * g_ptab[addr][k][v][o]
// (the pre-projected table already folds addr_emb @ enc_W). 128 threads x 8
// contiguous 20-float rows each, warp butterfly + smem reduce. Replaces the
// 256-iter stride-80B gather loop (35us -> ~4us).
// ---------------------------------------------------------------------------
__global__ void __launch_bounds__(128) phase3b(
    const float* __restrict__ enc_b,
    const float* __restrict__ d1_W, const float* __restrict__ d1_b,
    const float* __restrict__ d2_W, const float* __restrict__ d2_b,
    float* __restrict__ out)
{
    __shared__ float ps[1024];
    __shared__ float wsum[4][20];
    __shared__ float fr_in[60];
    __shared__ float r1[10];

    int b = blockIdx.x, tid = threadIdx.x;
    for (int i = tid; i < 1024; i += 128) {
        int k = i >> 8, v = i & 255;
        ps[i] = out[(k * 64 + b) * 256 + v];
    }
    __syncthreads();

    float acc[20];
    #pragma unroll
    for (int e = 0; e < 20; e++) acc[e] = 0.f;
    const float* ptA = g_ptab + 4 * 256 * 20;    // addr table
    #pragma unroll
    for (int it = 0; it < 8; it++) {
        int i = tid + it * 128;                  // flat (k,v) = k*256+v
        float p = ps[i];
        const float4* row = (const float4*)(ptA + i * 20);
        float4 r0 = __ldg(row),     r1v = __ldg(row + 1), r2 = __ldg(row + 2),
               r3 = __ldg(row + 3), r4  = __ldg(row + 4);
        acc[0]  += p * r0.x;  acc[1]  += p * r0.y;
        acc[2]  += p * r0.z;  acc[3]  += p * r0.w;
        acc[4]  += p * r1v.x; acc[5]  += p * r1v.y;
        acc[6]  += p * r1v.z; acc[7]  += p * r1v.w;
        acc[8]  += p * r2.x;  acc[9]  += p * r2.y;
        acc[10] += p * r2.z;  acc[11] += p * r2.w;
        acc[12] += p * r3.x;  acc[13] += p * r3.y;
        acc[14] += p * r3.z;  acc[15] += p * r3.w;
        acc[16] += p * r4.x;  acc[17] += p * r4.y;
        acc[18] += p * r4.z;  acc[19] += p * r4.w;
    }
    #pragma unroll
    for (int e = 0; e < 20; e++) {
        float v = acc[e];
        v += __shfl_xor_sync(0xffffffffu, v, 16);
        v += __shfl_xor_sync(0xffffffffu, v, 8);
        v += __shfl_xor_sync(0xffffffffu, v, 4);
        v += __shfl_xor_sync(0xffffffffu, v, 2);
        v += __shfl_xor_sync(0xffffffffu, v, 1);
        if ((tid & 31) == 0) wsum[tid >> 5][e] = v;
    }
    __syncthreads();

    if (tid < 20) {
        float a = wsum[0][tid] + wsum[1][tid] + wsum[2][tid] + wsum[3][tid]
                + enc_b[tid];
        fr_in[tid] = fsig(a);
    }
    if (tid >= 64 && tid < 104) {
        int e = tid - 64;
        fr_in[20 + e] = g_dist[b * 40 + e] * (1.0f / 4096.0f);
    }
    __syncthreads();

    if (tid < 10) {
        float a = d1_b[tid];
        #pragma unroll
        for (int e = 0; e < 60; e++) a += fr_in[e] * d1_W[tid * 60 + e];
        r1[tid] = fmaxf(a, 0.f);
    }
    __syncthreads();

    if (tid < 2) {
        float a = d2_b[tid];
        #pragma unroll
        for (int e = 0; e < 10; e++) a += r1[e] * d2_W[tid * 10 + e];
        out[131072 + tid * 64 + b] = a;
    }
}

// ---------------------------------------------------------------------------
extern "C" void kernel_launch(void* const* d_in, const int* in_sizes, int n_in,
                              void* d_out, int out_size)
{
    const int*   inp      = (const int*)d_in[0];
    const float* h0       = (const float*)d_in[1];
    const float* c0       = (const float*)d_in[2];
    const float* pc_emb   = (const float*)d_in[3];
    const float* addr_emb = (const float*)d_in[4];
    const float* enc_W    = (const float*)d_in[5];
    const float* enc_b    = (const float*)d_in[6];
    const float* W_ih     = (const float*)d_in[7];
    const float* W_hh     = (const float*)d_in[8];
    const float* b_ih     = (const float*)d_in[9];
    const float* b_hh     = (const float*)d_in[10];
    const float* dec_W    = (const float*)d_in[11];
    const float* dec_b    = (const float*)d_in[12];
    const float* d1_W     = (const float*)d_in[13];
    const float* d1_b     = (const float*)d_in[14];
    const float* d2_W     = (const float*)d_in[15];
    const float* d2_b     = (const float*)d_in[16];
    float* out = (float*)d_out;

    initk<<<10, 256>>>();
    prep<<<8, 256>>>(pc_emb, addr_emb, enc_W);
    phase1<<<dim3(8, 64), 256>>>(inp, enc_b, W_ih, b_ih, b_hh);
    phase2<<<64, 32>>>(h0, c0, W_hh);
    phase3a<<<128, 256>>>(dec_W, dec_b, out);
    phase3b<<<64, 128>>>(enc_b, d1_W, d1_b, d2_W, d2_b, out);
}